// round 1
// baseline (speedup 1.0000x reference)
#include <cuda_runtime.h>
#include <math.h>

// Problem constants (fixed shapes from reference setup_inputs)
#define BB   64
#define AA   3
#define CC   11
#define HH   80
#define WW   80
#define TT   50
#define HWSZ (HH * WW)                // 6400
#define NCH  (AA * (5 + CC))          // 48
#define CPA  (5 + CC)                 // 16 channels per anchor
#define NTOT (BB * AA * HWSZ)         // 1,228,800
#define NTGT (BB * TT)                // 3200
#define EPSF 1e-7f

// Scratch (no allocations allowed)
__device__ __align__(16) unsigned char g_mask[NTOT];
// acc[0]=loss_box, acc[1]=loss_cls, acc[2]=sum_softplus, acc[3]=sum_weighted_masked
__device__ double g_acc[4];

__device__ __forceinline__ float softplusf(float x) {
    // logaddexp(0, x) = max(x,0) + log1p(exp(-|x|))
    return fmaxf(x, 0.0f) + log1pf(expf(-fabsf(x)));
}

__device__ __forceinline__ float sigmoidf(float x) {
    return 1.0f / (1.0f + expf(-x));
}

__device__ __forceinline__ float warp_sum(float v) {
#pragma unroll
    for (int o = 16; o > 0; o >>= 1) v += __shfl_down_sync(0xffffffffu, v, o);
    return v;
}

// ---------------------------------------------------------------------------
__global__ void k_init() {
    int i = blockIdx.x * blockDim.x + threadIdx.x;
    uint4* m4 = reinterpret_cast<uint4*>(g_mask);
    const int n4 = NTOT / 16;  // 76800
    if (i < n4) m4[i] = make_uint4(0u, 0u, 0u, 0u);
    if (i < 4) g_acc[i] = 0.0;
}

// ---------------------------------------------------------------------------
// Robust scalar load: handles int32, int64 (LE low word), or float32 encoding.
__device__ __forceinline__ float load_stride(const void* p) {
    int iv = *reinterpret_cast<const int*>(p);
    if (iv > 0 && iv < 100000) return (float)iv;   // plausible integer stride
    return __int_as_float(iv);                      // else it was a float
}

__global__ void k_targets(const float* __restrict__ pred,
                          const float* __restrict__ boxes,
                          const int*   __restrict__ classes,
                          const float* __restrict__ anchors,
                          const void*  __restrict__ stride_p) {
    int i = blockIdx.x * blockDim.x + threadIdx.x;  // 0..NTGT-1
    float lb = 0.0f, lc = 0.0f;

    if (i < NTGT) {
        const int b = i / TT;
        const float s = load_stride(stride_p);
        const float inv_s = 1.0f / s;

        const float4 bx = *reinterpret_cast<const float4*>(boxes + (size_t)i * 4);
        const float x1 = bx.x, y1 = bx.y, x2 = bx.z, y2 = bx.w;
        const float cx = (x1 + x2) * 0.5f, cy = (y1 + y2) * 0.5f;
        const float tw = x2 - x1, th = y2 - y1;

        const float gx = cx * inv_s, gy = cy * inv_s;
        const float gw = tw * inv_s, gh = th * inv_s;
        const int gi = (int)gx;   // truncation (gx >= 0)
        const int gj = (int)gy;
        const bool valid = (gi >= 0) && (gi < WW) && (gj >= 0) && (gj < HH);
        const int gi_c = min(max(gi, 0), WW - 1);
        const int gj_c = min(max(gj, 0), HH - 1);

        // anchor argmin over penalty, first-min wins
        int best = 0;
        float best_pen = 3.402823e38f;
#pragma unroll
        for (int a = 0; a < AA; a++) {
            const float aw_ = anchors[2 * a], ah_ = anchors[2 * a + 1];
            const float rw = gw / aw_, rh = gh / ah_;
            const float pw_ = fmaxf(rw, 1.0f / rw);
            const float ph_ = fmaxf(rh, 1.0f / rh);
            const float pen = fmaxf(pw_, ph_);
            if (pen < best_pen) { best_pen = pen; best = a; }
        }
        const float aw = anchors[2 * best], ah = anchors[2 * best + 1];

        const size_t base = (size_t)(b * NCH + best * CPA) * HWSZ
                          + (size_t)gj_c * WW + gi_c;

        const float p0 = pred[base];
        const float p1 = pred[base + 1 * HWSZ];
        const float p2 = pred[base + 2 * HWSZ];
        const float p3 = pred[base + 3 * HWSZ];

        const float px = sigmoidf(p0) + (float)gi_c;
        const float py = sigmoidf(p1) + (float)gj_c;
        const float pw = expf(p2) * aw;
        const float ph = expf(p3) * ah;

        const float px1 = (px - pw * 0.5f) * s;
        const float py1 = (py - ph * 0.5f) * s;
        const float px2 = (px + pw * 0.5f) * s;
        const float py2 = (py + ph * 0.5f) * s;

        // CIoU
        const float iw = fmaxf(fminf(px2, x2) - fmaxf(px1, x1), 0.0f);
        const float ih = fmaxf(fminf(py2, y2) - fmaxf(py1, y1), 0.0f);
        const float inter = iw * ih;
        const float pa = (px2 - px1) * (py2 - py1);
        const float ta = tw * th;
        const float uni = pa + ta - inter + EPSF;
        const float iou = inter / uni;
        const float cw = fmaxf(px2, x2) - fminf(px1, x1);
        const float chh = fmaxf(py2, y2) - fminf(py1, y1);
        const float c2 = cw * cw + chh * chh + EPSF;
        const float dx = px1 + px2 - x1 - x2;
        const float dy = py1 + py2 - y1 - y2;
        const float rho2 = (dx * dx + dy * dy) * 0.25f;
        const float k4pi2 = 4.0f / (float)(M_PI * M_PI);
        const float dat = atanf(tw / (th + EPSF)) - atanf((px2 - px1) / ((py2 - py1) + EPSF));
        const float v = k4pi2 * dat * dat;
        const float alpha = v / (v - iou + 1.0f + EPSF);
        const float ciou = 1.0f - iou + rho2 / c2 + alpha * v;

        // classification BCE vs one-hot
        const int cls_t = classes[i];
        float cls_sum = 0.0f;
#pragma unroll
        for (int c = 0; c < CC; c++) {
            const float x = pred[base + (size_t)(5 + c) * HWSZ];
            const float tgt = (c == cls_t) ? 1.0f : 0.0f;
            cls_sum += softplusf(x) - x * tgt;
        }

        if (valid) {
            lb = ciou;
            lc = cls_sum;
            g_mask[(size_t)(b * AA + best) * HWSZ + (size_t)gj_c * WW + gi_c] = 1;
        }
    }

    // block reduce -> double atomics
    __shared__ float s_lb[8], s_lc[8];
    const int wid = threadIdx.x >> 5, lane = threadIdx.x & 31;
    float rb = warp_sum(lb), rc = warp_sum(lc);
    if (lane == 0) { s_lb[wid] = rb; s_lc[wid] = rc; }
    __syncthreads();
    if (threadIdx.x == 0) {
        float tb = 0.0f, tc = 0.0f;
        const int nw = (blockDim.x + 31) >> 5;
        for (int w = 0; w < nw; w++) { tb += s_lb[w]; tc += s_lc[w]; }
        atomicAdd(&g_acc[0], (double)tb);
        atomicAdd(&g_acc[1], (double)tc);
    }
}

// ---------------------------------------------------------------------------
__global__ void k_obj(const float* __restrict__ pred) {
    const int i = blockIdx.x * blockDim.x + threadIdx.x;  // handles 4 elements
    float ssp = 0.0f, swm = 0.0f;
    if (i < NTOT / 4) {
        const int e = i * 4;
        const int b   = e / (AA * HWSZ);
        const int rem = e - b * (AA * HWSZ);
        const int a   = rem / HWSZ;
        const int hw  = rem - a * HWSZ;
        const float4 v = *reinterpret_cast<const float4*>(
            pred + (size_t)(b * NCH + a * CPA + 4) * HWSZ + hw);
        const uchar4 m = *reinterpret_cast<const uchar4*>(g_mask + e);
        ssp = softplusf(v.x) + softplusf(v.y) + softplusf(v.z) + softplusf(v.w);
        const float wb = (float)(BB - b);
        swm = wb * (v.x * (float)m.x + v.y * (float)m.y +
                    v.z * (float)m.z + v.w * (float)m.w);
    }
    __shared__ float s_sp[8], s_wm[8];
    const int wid = threadIdx.x >> 5, lane = threadIdx.x & 31;
    float rs = warp_sum(ssp), rw = warp_sum(swm);
    if (lane == 0) { s_sp[wid] = rs; s_wm[wid] = rw; }
    __syncthreads();
    if (threadIdx.x == 0) {
        float t1 = 0.0f, t2 = 0.0f;
        const int nw = (blockDim.x + 31) >> 5;
        for (int w = 0; w < nw; w++) { t1 += s_sp[w]; t2 += s_wm[w]; }
        atomicAdd(&g_acc[2], (double)t1);
        atomicAdd(&g_acc[3], (double)t2);
    }
}

// ---------------------------------------------------------------------------
__global__ void k_final(float* __restrict__ out) {
    const double loss_box = g_acc[0];
    const double loss_cls = g_acc[1];
    const double sp_sum   = g_acc[2];
    const double wm       = g_acc[3];
    const double n_tot = (double)NTOT;
    const double loss_obj = ((double)BB * sp_sum - wm) / n_tot;
    const double num_targets = (double)(BB * TT);
    const double total = 5.0 * loss_box / num_targets
                       + loss_obj / (double)BB
                       + 1.0 * loss_cls / num_targets;
    out[0] = (float)total;
}

// ---------------------------------------------------------------------------
extern "C" void kernel_launch(void* const* d_in, const int* in_sizes, int n_in,
                              void* d_out, int out_size) {
    const float* pred    = (const float*)d_in[0];
    const float* boxes   = (const float*)d_in[1];
    const int*   classes = (const int*)  d_in[2];
    const float* anchors = (const float*)d_in[3];
    const void*  stridep = (n_in > 4) ? d_in[4] : nullptr;
    float* out = (float*)d_out;
    (void)in_sizes; (void)out_size;

    k_init<<<(NTOT / 16 + 255) / 256, 256>>>();
    k_targets<<<(NTGT + 255) / 256, 256>>>(pred, boxes, classes, anchors, stridep);
    k_obj<<<(NTOT / 4 + 255) / 256, 256>>>(pred);
    k_final<<<1, 1>>>(out);
}